// round 1
// baseline (speedup 1.0000x reference)
#include <cuda_runtime.h>
#include <cstddef>

// Problem constants
#define NN 64
#define CC 64
#define TDIM 300
#define VV 25
#define IC 16
#define NS 3
#define TT 4                    // t-values per block in kernel A
#define POS_PER_N (TDIM * VV)   // 7500
#define BN_EPS 1e-5f

// Scratch: scale[i][n][t][v]  (3*64*300*25 floats = 5.76 MB)
__device__ float g_scale_buf[NS * NN * POS_PER_N];

// ---------------------------------------------------------------------------
// Kernel A: fused a/b projections + attention logits + softmax + column sum.
// grid (75, 64), block 128 threads, dynamic smem.
//
// Per (n, t):
//   proj rows r in [0,96): r<48 -> aP[i*16+j], r>=48 -> bP  ; proj[r][u], u in [0,25)
//   logits[i][u][w] = (1/16) * sum_j aP[i,j,u] * bP[i,j,w]
//   P = softmax over w per (i,u) row
//   scale[i][w] = sum_u P[u][w] + sum_u (A+GA)[i][u][w]
// ---------------------------------------------------------------------------
__global__ void __launch_bounds__(128) kA(
    const float* __restrict__ x,     // [N, C, T, V]
    const float* __restrict__ A,     // [3, V, V]
    const float* __restrict__ GA,    // [3, V, V]
    const float* __restrict__ a_w,   // [3, 16, 64]
    const float* __restrict__ a_b,   // [3, 16]
    const float* __restrict__ b_w,   // [3, 16, 64]
    const float* __restrict__ b_b)   // [3, 16]
{
    extern __shared__ float sm[];
    float* swT   = sm;                  // [64][96]  weights transposed (c, r) : 6144
    float* xs    = swT + 64 * 96;       // [64][100] x chunk (c, tl*25+v)      : 6400
    float* proj  = xs + 6400;           // [96][26]                            : 2496
    float* logit = proj + 96 * 26;      // [75][26]  (i*25+u) x w              : 1950
    float* colAF = logit + 75 * 26;     // [96] (75 used)
    float* pbias = colAF + 96;          // [96]

    const int n     = blockIdx.y;
    const int tbase = blockIdx.x * TT;
    const int tid   = threadIdx.x;

    // Load weights transposed: swT[c*96 + r]
    for (int e = tid; e < 96 * 64; e += 128) {
        int r = e % 96, c = e / 96;
        float w = (r < 48) ? a_w[r * 64 + c] : b_w[(r - 48) * 64 + c];
        swT[c * 96 + r] = w;
    }
    if (tid < 96) pbias[tid] = (tid < 48) ? a_b[tid] : b_b[tid - 48];

    // Column sums of A_full = A + GA :  colAF[i*25 + w] = sum_u (A+GA)[i][u][w]
    if (tid < 75) {
        int i = tid / 25, w = tid % 25;
        float s = 0.f;
        #pragma unroll
        for (int u = 0; u < 25; ++u) {
            int idx = (i * 25 + u) * 25 + w;
            s += A[idx] + GA[idx];
        }
        colAF[tid] = s;
    }

    // Load x chunk: xs[c*100 + p], p = local (t,v) flattened (contiguous in gmem)
    const float* xn = x + (size_t)n * (CC * POS_PER_N) + (size_t)tbase * VV;
    for (int e = tid; e < 6400; e += 128) {
        int c = e / 100, p = e % 100;
        xs[e] = xn[(size_t)c * POS_PER_N + p];
    }
    __syncthreads();

    for (int tl = 0; tl < TT; ++tl) {
        const int toff = tl * 25;

        // -------- Phase 1: projections (96 rows x 25 u), tile 4r x 5u, 120 thr
        if (tid < 120) {
            const int rg = tid / 5;
            const int ug = tid - rg * 5;
            const int r0 = rg * 4;
            const int u0 = ug * 5;

            float acc[4][5];
            #pragma unroll
            for (int a = 0; a < 4; ++a) {
                float bv = pbias[r0 + a];
                #pragma unroll
                for (int b = 0; b < 5; ++b) acc[a][b] = bv;
            }
            const float* xcol = xs + toff + u0;
            const float* wcol = swT + r0;
            #pragma unroll 4
            for (int c = 0; c < 64; ++c) {
                const float4 w4 = *reinterpret_cast<const float4*>(wcol + c * 96);
                float xv[5];
                #pragma unroll
                for (int b = 0; b < 5; ++b) xv[b] = xcol[c * 100 + b];
                #pragma unroll
                for (int b = 0; b < 5; ++b) {
                    acc[0][b] = fmaf(w4.x, xv[b], acc[0][b]);
                    acc[1][b] = fmaf(w4.y, xv[b], acc[1][b]);
                    acc[2][b] = fmaf(w4.z, xv[b], acc[2][b]);
                    acc[3][b] = fmaf(w4.w, xv[b], acc[3][b]);
                }
            }
            #pragma unroll
            for (int a = 0; a < 4; ++a)
                #pragma unroll
                for (int b = 0; b < 5; ++b)
                    proj[(r0 + a) * 26 + u0 + b] = acc[a][b];
        }
        __syncthreads();

        // -------- Phase 2: logits [3][25][25]
        for (int e = tid; e < 1875; e += 128) {
            int i   = e / 625;
            int rem = e - i * 625;
            int u   = rem / 25;
            int w   = rem - u * 25;
            const float* ap = proj + (i * 16) * 26 + u;
            const float* bp = proj + (48 + i * 16) * 26 + w;
            float s = 0.f;
            #pragma unroll
            for (int j = 0; j < 16; ++j) s = fmaf(ap[j * 26], bp[j * 26], s);
            logit[(i * 25 + u) * 26 + w] = s * (1.0f / 16.0f);
        }
        __syncthreads();

        // -------- Phase 3: softmax over w for each of 75 rows (i,u)
        if (tid < 75) {
            float* row = logit + tid * 26;
            float m = row[0];
            #pragma unroll
            for (int w = 1; w < 25; ++w) m = fmaxf(m, row[w]);
            float ev[25];
            float s = 0.f;
            #pragma unroll
            for (int w = 0; w < 25; ++w) { float e = __expf(row[w] - m); ev[w] = e; s += e; }
            float inv = 1.0f / s;
            #pragma unroll
            for (int w = 0; w < 25; ++w) row[w] = ev[w] * inv;
        }
        __syncthreads();

        // -------- Phase 4: column sums + write scale
        if (tid < 75) {
            int i = tid / 25, w = tid - (tid / 25) * 25;
            float s = colAF[tid];
            #pragma unroll
            for (int u = 0; u < 25; ++u) s += logit[(i * 25 + u) * 26 + w];
            int t = tbase + tl;
            g_scale_buf[((size_t)i * NN + n) * POS_PER_N + t * VV + w] = s;
        }
        __syncthreads();
    }
}

// ---------------------------------------------------------------------------
// Kernel B: hidden = sum_i scale_i * (g_w[i] @ x) + sum_i g_b[i]
//           out    = relu( BN(hidden) + x )
// grid (75, 64), block 320 threads (16 o-groups x 20 p-groups), tile 4o x 5p.
// ---------------------------------------------------------------------------
__global__ void __launch_bounds__(320) kB(
    const float* __restrict__ x,     // [N, C, T, V]
    const float* __restrict__ g_w,   // [3, 64, 64]
    const float* __restrict__ g_b,   // [3, 64]
    const float* __restrict__ bn_g,
    const float* __restrict__ bn_b,
    const float* __restrict__ bn_m,
    const float* __restrict__ bn_v,
    float* __restrict__ out)         // [N, C, T, V]
{
    extern __shared__ float sm[];
    float* gwT = sm;                    // [3][64][68] transposed (i,c,o), pad 68 : 13056
    float* xs  = gwT + 3 * 64 * 68;     // [64][100]                              : 6400
    float* ss  = xs + 6400;             // [3][100] scales                        : 300
    float* gbs = ss + 300;              // [64] sum of g_b over i
    float* bnA = gbs + 64;              // [64] gamma * rsqrt(var+eps)
    float* bnB = bnA + 64;              // [64] beta - mean * bnA

    const int n     = blockIdx.y;
    const int pbase = blockIdx.x * 100;
    const int tid   = threadIdx.x;

    // g_w transposed into shared: gwT[(i*64 + c)*68 + o] = g_w[i][o][c]
    for (int e = tid; e < 3 * 64 * 64; e += 320) {
        int c = e & 63;
        int o = (e >> 6) & 63;
        int i = e >> 12;
        gwT[(i * 64 + c) * 68 + o] = g_w[(i * 64 + o) * 64 + c];
    }
    // x chunk
    const float* xn = x + (size_t)n * (CC * POS_PER_N) + pbase;
    for (int e = tid; e < 6400; e += 320) {
        int c = e / 100, p = e % 100;
        xs[e] = xn[(size_t)c * POS_PER_N + p];
    }
    // scales
    for (int e = tid; e < 300; e += 320) {
        int i = e / 100, p = e % 100;
        ss[e] = g_scale_buf[((size_t)i * NN + n) * POS_PER_N + pbase + p];
    }
    // per-channel params
    if (tid < 64) {
        float a = bn_g[tid] * rsqrtf(bn_v[tid] + BN_EPS);
        bnA[tid] = a;
        bnB[tid] = bn_b[tid] - bn_m[tid] * a;
        gbs[tid] = g_b[tid] + g_b[64 + tid] + g_b[128 + tid];
    }
    __syncthreads();

    const int og = tid / 20;        // 0..15
    const int pg = tid - og * 20;   // 0..19  -> p = pg + 20*b (interleaved)
    const int o0 = og * 4;

    float acc[4][5];
    #pragma unroll
    for (int a = 0; a < 4; ++a) {
        float g = gbs[o0 + a];
        #pragma unroll
        for (int b = 0; b < 5; ++b) acc[a][b] = g;
    }

    #pragma unroll
    for (int i = 0; i < 3; ++i) {
        float y[4][5];
        #pragma unroll
        for (int a = 0; a < 4; ++a)
            #pragma unroll
            for (int b = 0; b < 5; ++b) y[a][b] = 0.f;

        const float* gw = gwT + i * (64 * 68) + o0;
        const float* xc = xs + pg;
        #pragma unroll 4
        for (int c = 0; c < 64; ++c) {
            const float4 w4 = *reinterpret_cast<const float4*>(gw + c * 68);
            float xv[5];
            #pragma unroll
            for (int b = 0; b < 5; ++b) xv[b] = xc[c * 100 + 20 * b];
            #pragma unroll
            for (int b = 0; b < 5; ++b) {
                y[0][b] = fmaf(w4.x, xv[b], y[0][b]);
                y[1][b] = fmaf(w4.y, xv[b], y[1][b]);
                y[2][b] = fmaf(w4.z, xv[b], y[2][b]);
                y[3][b] = fmaf(w4.w, xv[b], y[3][b]);
            }
        }
        const float* sp = ss + i * 100 + pg;
        #pragma unroll
        for (int b = 0; b < 5; ++b) {
            float sv = sp[20 * b];
            #pragma unroll
            for (int a = 0; a < 4; ++a) acc[a][b] = fmaf(y[a][b], sv, acc[a][b]);
        }
    }

    // Epilogue: BN + residual + relu, coalesced stores (lanes contiguous in pg)
    float* outn = out + (size_t)n * (CC * POS_PER_N) + pbase;
    #pragma unroll
    for (int a = 0; a < 4; ++a) {
        const int o = o0 + a;
        const float bA = bnA[o];
        const float bB = bnB[o];
        #pragma unroll
        for (int b = 0; b < 5; ++b) {
            const int p = pg + 20 * b;
            float h = fmaf(acc[a][b], bA, bB) + xs[o * 100 + p];
            outn[(size_t)o * POS_PER_N + p] = fmaxf(h, 0.0f);
        }
    }
}

// ---------------------------------------------------------------------------
extern "C" void kernel_launch(void* const* d_in, const int* in_sizes, int n_in,
                              void* d_out, int out_size) {
    const float* x    = (const float*)d_in[0];
    const float* A    = (const float*)d_in[1];
    const float* GA   = (const float*)d_in[2];
    const float* g_w  = (const float*)d_in[3];
    const float* g_b  = (const float*)d_in[4];
    const float* a_w  = (const float*)d_in[5];
    const float* a_b  = (const float*)d_in[6];
    const float* b_w  = (const float*)d_in[7];
    const float* b_b  = (const float*)d_in[8];
    const float* bn_g = (const float*)d_in[9];
    const float* bn_b = (const float*)d_in[10];
    const float* bn_m = (const float*)d_in[11];
    const float* bn_v = (const float*)d_in[12];
    float* out = (float*)d_out;

    const size_t smA = (size_t)(6144 + 6400 + 2496 + 1950 + 96 + 96) * sizeof(float);   // 68728 B
    const size_t smB = (size_t)(13056 + 6400 + 300 + 64 + 64 + 64) * sizeof(float);     // 79952 B

    cudaFuncSetAttribute(kA, cudaFuncAttributeMaxDynamicSharedMemorySize, (int)smA);
    cudaFuncSetAttribute(kB, cudaFuncAttributeMaxDynamicSharedMemorySize, (int)smB);

    dim3 grid(TDIM / TT, NN);   // (75, 64)
    kA<<<grid, 128, smA>>>(x, A, GA, a_w, a_b, b_w, b_b);

    dim3 gridB(POS_PER_N / 100, NN);  // (75, 64)
    kB<<<gridB, 320, smB>>>(x, g_w, g_b, bn_g, bn_b, bn_m, bn_v, out);
}

// round 2
// speedup vs baseline: 1.0767x; 1.0767x over previous
#include <cuda_runtime.h>
#include <cstddef>

#define NN 64
#define CC 64
#define TDIM 300
#define VV 25
#define NS 3
#define POS_PER_N (TDIM * VV)   // 7500
#define BN_EPS 1e-5f

typedef unsigned long long u64;

__device__ float g_scale_buf[NS * NN * POS_PER_N];  // 5.76 MB scratch

// ---------------- f32x2 helpers ----------------
__device__ __forceinline__ u64 pack2(float lo, float hi) {
    u64 r; asm("mov.b64 %0, {%1, %2};" : "=l"(r) : "f"(lo), "f"(hi)); return r;
}
__device__ __forceinline__ u64 splat2(float v) { return pack2(v, v); }
__device__ __forceinline__ void unpack2(u64 v, float& lo, float& hi) {
    asm("mov.b64 {%0, %1}, %2;" : "=f"(lo), "=f"(hi) : "l"(v));
}
__device__ __forceinline__ void fma2(u64& d, u64 a, u64 b) {
    asm("fma.rn.f32x2 %0, %1, %2, %0;" : "+l"(d) : "l"(a), "l"(b));
}

// ---------------------------------------------------------------------------
// Kernel A: fused a/b projections (f32x2 GEMM over all 4 t at once) +
// attention logits + softmax + column-sum -> scale scratch.
// grid (75, 64), block 256.
// ---------------------------------------------------------------------------
__global__ void __launch_bounds__(256) kA(
    const float* __restrict__ x,     // [N, C, T, V]
    const float* __restrict__ A,     // [3, V, V]
    const float* __restrict__ GA,    // [3, V, V]
    const float* __restrict__ a_w,   // [3, 16, 64] -> [48][64]
    const float* __restrict__ a_b,   // [48]
    const float* __restrict__ b_w,   // [48][64]
    const float* __restrict__ b_b)   // [48]
{
    extern __shared__ float sm[];
    float* swT   = sm;               // [64][96]  (c, r)
    float* xs    = swT + 6144;       // [64][100] (c, tl*25+v)
    float* proj  = xs + 6400;        // [96][100]
    float* logit = proj + 9600;      // [75][26]
    float* colAF = logit + 1950;     // [75]
    float* pbias = colAF + 75;       // [96]

    const int n     = blockIdx.y;
    const int tbase = blockIdx.x * 4;
    const int tid   = threadIdx.x;

    // weights transposed
    for (int e = tid; e < 96 * 64; e += 256) {
        int r = e % 96, c = e / 96;
        swT[c * 96 + r] = (r < 48) ? a_w[r * 64 + c] : b_w[(r - 48) * 64 + c];
    }
    if (tid < 96) pbias[tid] = (tid < 48) ? a_b[tid] : b_b[tid - 48];

    if (tid < 75) {
        int i = tid / 25, w = tid % 25;
        float s = 0.f;
        #pragma unroll
        for (int u = 0; u < 25; ++u) {
            int idx = (i * 25 + u) * 25 + w;
            s += A[idx] + GA[idx];
        }
        colAF[tid] = s;
    }

    // x chunk (4 t x 25 v = 100 contiguous positions)
    const float* xn = x + (size_t)n * (CC * POS_PER_N) + (size_t)tbase * VV;
    for (int e = tid; e < 6400; e += 256) {
        int c = e / 100, p = e % 100;
        xs[e] = xn[(size_t)c * POS_PER_N + p];
    }
    __syncthreads();

    // ---- Phase 1: projections, 240 threads, tile 4r x 5 col-pairs (f32x2)
    if (tid < 240) {
        const int rg = tid / 10;
        const int cg = tid - rg * 10;
        const int r0 = rg * 4;
        const int p0 = 2 * cg;

        u64 acc[4][5];
        #pragma unroll
        for (int a = 0; a < 4; ++a) {
            u64 bv = splat2(pbias[r0 + a]);
            #pragma unroll
            for (int b = 0; b < 5; ++b) acc[a][b] = bv;
        }
        #pragma unroll 4
        for (int c = 0; c < 64; ++c) {
            const float4 w4 = *reinterpret_cast<const float4*>(swT + c * 96 + r0);
            u64 ws[4];
            ws[0] = splat2(w4.x); ws[1] = splat2(w4.y);
            ws[2] = splat2(w4.z); ws[3] = splat2(w4.w);
            u64 xv[5];
            #pragma unroll
            for (int b = 0; b < 5; ++b)
                xv[b] = *reinterpret_cast<const u64*>(xs + c * 100 + p0 + 20 * b);
            #pragma unroll
            for (int b = 0; b < 5; ++b) {
                fma2(acc[0][b], ws[0], xv[b]);
                fma2(acc[1][b], ws[1], xv[b]);
                fma2(acc[2][b], ws[2], xv[b]);
                fma2(acc[3][b], ws[3], xv[b]);
            }
        }
        #pragma unroll
        for (int a = 0; a < 4; ++a)
            #pragma unroll
            for (int b = 0; b < 5; ++b)
                *reinterpret_cast<u64*>(proj + (r0 + a) * 100 + p0 + 20 * b) = acc[a][b];
    }
    __syncthreads();

    // ---- Phases 2-4 per t
    for (int tl = 0; tl < 4; ++tl) {
        const int toff = tl * 25;

        // logits [3][25][25]
        for (int e = tid; e < 1875; e += 256) {
            int i   = e / 625;
            int rem = e - i * 625;
            int u   = rem / 25;
            int w   = rem - u * 25;
            const float* ap = proj + (i * 16) * 100 + toff + u;
            const float* bp = proj + (48 + i * 16) * 100 + toff + w;
            float s = 0.f;
            #pragma unroll
            for (int j = 0; j < 16; ++j) s = fmaf(ap[j * 100], bp[j * 100], s);
            logit[(i * 25 + u) * 26 + w] = s * (1.0f / 16.0f);
        }
        __syncthreads();

        // softmax over w per row
        if (tid < 75) {
            float* row = logit + tid * 26;
            float m = row[0];
            #pragma unroll
            for (int w = 1; w < 25; ++w) m = fmaxf(m, row[w]);
            float s = 0.f;
            float ev[25];
            #pragma unroll
            for (int w = 0; w < 25; ++w) { float e = __expf(row[w] - m); ev[w] = e; s += e; }
            float inv = 1.0f / s;
            #pragma unroll
            for (int w = 0; w < 25; ++w) row[w] = ev[w] * inv;
        }
        __syncthreads();

        // column sums + write
        if (tid < 75) {
            int i = tid / 25, w = tid - (tid / 25) * 25;
            float s = colAF[tid];
            #pragma unroll
            for (int u = 0; u < 25; ++u) s += logit[(i * 25 + u) * 26 + w];
            g_scale_buf[((size_t)i * NN + n) * POS_PER_N + (tbase + tl) * VV + w] = s;
        }
        __syncthreads();
    }
}

// ---------------------------------------------------------------------------
// Kernel B: hidden = sum_i scale_i * (g_w[i] @ x) + gb ; out = relu(BN(h)+x)
// grid (38, 64), block 320 (two 160-thread halves over a 200-pos chunk).
// Tile per thread: 4o x 5 p-pairs (f32x2).
// ---------------------------------------------------------------------------
__global__ void __launch_bounds__(320) kB(
    const float* __restrict__ x,
    const float* __restrict__ g_w,   // [3][64][64]
    const float* __restrict__ g_b,   // [3][64]
    const float* __restrict__ bn_g,
    const float* __restrict__ bn_b,
    const float* __restrict__ bn_m,
    const float* __restrict__ bn_v,
    float* __restrict__ out)
{
    extern __shared__ float sm[];
    float* gwT = sm;                 // [3][64][68] (i, c, o) : 13056
    float* xs  = gwT + 13056;        // [64][200]            : 12800
    float* ss  = xs + 12800;         // [3][200]             : 600
    float* gbs = ss + 600;           // [64]
    float* bnA = gbs + 64;           // [64]
    float* bnB = bnA + 64;           // [64]

    const int n     = blockIdx.y;
    const int pbase = blockIdx.x * 200;
    const int tid   = threadIdx.x;

    for (int e = tid; e < 3 * 64 * 64; e += 320) {
        int c = e & 63;
        int o = (e >> 6) & 63;
        int i = e >> 12;
        gwT[(i * 64 + c) * 68 + o] = g_w[(i * 64 + o) * 64 + c];
    }
    const float* xn = x + (size_t)n * (CC * POS_PER_N) + pbase;
    for (int e = tid; e < 12800; e += 320) {
        int c = e / 200, p = e % 200;
        xs[e] = (pbase + p < POS_PER_N) ? xn[(size_t)c * POS_PER_N + p] : 0.f;
    }
    for (int e = tid; e < 600; e += 320) {
        int i = e / 200, p = e % 200;
        ss[e] = (pbase + p < POS_PER_N)
              ? g_scale_buf[((size_t)i * NN + n) * POS_PER_N + pbase + p] : 0.f;
    }
    if (tid < 64) {
        float a = bn_g[tid] * rsqrtf(bn_v[tid] + BN_EPS);
        bnA[tid] = a;
        bnB[tid] = bn_b[tid] - bn_m[tid] * a;
        gbs[tid] = g_b[tid] + g_b[64 + tid] + g_b[128 + tid];
    }
    __syncthreads();

    const int h  = tid / 160;            // which 100-pos half
    const int r  = tid - h * 160;
    const int og = r / 10;               // 0..15
    const int pg = r - og * 10;          // 0..9
    const int o0 = og * 4;
    const int p0 = h * 100 + 2 * pg;     // even

    u64 acc[4][5];
    #pragma unroll
    for (int a = 0; a < 4; ++a) {
        u64 g = splat2(gbs[o0 + a]);
        #pragma unroll
        for (int b = 0; b < 5; ++b) acc[a][b] = g;
    }

    #pragma unroll
    for (int i = 0; i < 3; ++i) {
        u64 y[4][5];
        #pragma unroll
        for (int a = 0; a < 4; ++a)
            #pragma unroll
            for (int b = 0; b < 5; ++b) y[a][b] = 0ull;

        const float* gw = gwT + i * (64 * 68) + o0;
        #pragma unroll 4
        for (int c = 0; c < 64; ++c) {
            const float4 w4 = *reinterpret_cast<const float4*>(gw + c * 68);
            u64 ws[4];
            ws[0] = splat2(w4.x); ws[1] = splat2(w4.y);
            ws[2] = splat2(w4.z); ws[3] = splat2(w4.w);
            u64 xv[5];
            #pragma unroll
            for (int b = 0; b < 5; ++b)
                xv[b] = *reinterpret_cast<const u64*>(xs + c * 200 + p0 + 20 * b);
            #pragma unroll
            for (int b = 0; b < 5; ++b) {
                fma2(y[0][b], ws[0], xv[b]);
                fma2(y[1][b], ws[1], xv[b]);
                fma2(y[2][b], ws[2], xv[b]);
                fma2(y[3][b], ws[3], xv[b]);
            }
        }
        #pragma unroll
        for (int b = 0; b < 5; ++b) {
            u64 s2 = *reinterpret_cast<const u64*>(ss + i * 200 + p0 + 20 * b);
            #pragma unroll
            for (int a = 0; a < 4; ++a) fma2(acc[a][b], y[a][b], s2);
        }
    }

    // Epilogue: BN + residual + relu
    float* outn = out + (size_t)n * (CC * POS_PER_N) + pbase;
    #pragma unroll
    for (int a = 0; a < 4; ++a) {
        const int o = o0 + a;
        const float bA = bnA[o];
        const float bB = bnB[o];
        #pragma unroll
        for (int b = 0; b < 5; ++b) {
            const int p = p0 + 20 * b;
            if (pbase + p < POS_PER_N) {
                float f0, f1;
                unpack2(acc[a][b], f0, f1);
                const float2 xr = *reinterpret_cast<const float2*>(xs + o * 200 + p);
                float h0 = fmaf(f0, bA, bB) + xr.x;
                float h1 = fmaf(f1, bA, bB) + xr.y;
                float2 res;
                res.x = fmaxf(h0, 0.f);
                res.y = fmaxf(h1, 0.f);
                *reinterpret_cast<float2*>(outn + (size_t)o * POS_PER_N + p) = res;
            }
        }
    }
}

// ---------------------------------------------------------------------------
extern "C" void kernel_launch(void* const* d_in, const int* in_sizes, int n_in,
                              void* d_out, int out_size) {
    const float* x    = (const float*)d_in[0];
    const float* A    = (const float*)d_in[1];
    const float* GA   = (const float*)d_in[2];
    const float* g_w  = (const float*)d_in[3];
    const float* g_b  = (const float*)d_in[4];
    const float* a_w  = (const float*)d_in[5];
    const float* a_b  = (const float*)d_in[6];
    const float* b_w  = (const float*)d_in[7];
    const float* b_b  = (const float*)d_in[8];
    const float* bn_g = (const float*)d_in[9];
    const float* bn_b = (const float*)d_in[10];
    const float* bn_m = (const float*)d_in[11];
    const float* bn_v = (const float*)d_in[12];
    float* out = (float*)d_out;

    const size_t smA = (size_t)(6144 + 6400 + 9600 + 1950 + 75 + 96) * sizeof(float);   // 97060 B
    const size_t smB = (size_t)(13056 + 12800 + 600 + 64 + 64 + 64) * sizeof(float);    // 106592 B

    cudaFuncSetAttribute(kA, cudaFuncAttributeMaxDynamicSharedMemorySize, (int)smA);
    cudaFuncSetAttribute(kB, cudaFuncAttributeMaxDynamicSharedMemorySize, (int)smB);

    dim3 gridA(TDIM / 4, NN);                  // (75, 64)
    kA<<<gridA, 256, smA>>>(x, A, GA, a_w, a_b, b_w, b_b);

    dim3 gridB((POS_PER_N + 199) / 200, NN);   // (38, 64)
    kB<<<gridB, 320, smB>>>(x, g_w, g_b, bn_g, bn_b, bn_m, bn_v, out);
}